// round 2
// baseline (speedup 1.0000x reference)
#include <cuda_runtime.h>
#include <math.h>

#define BLOCK 256
#define NELEM 4096
#define K (NELEM / BLOCK)
#define NWARP (BLOCK / 32)

__device__ __forceinline__ float wsum(float v) {
#pragma unroll
    for (int o = 16; o > 0; o >>= 1) v += __shfl_down_sync(0xffffffffu, v, o);
    return v;
}
__device__ __forceinline__ float wmin(float v) {
#pragma unroll
    for (int o = 16; o > 0; o >>= 1) v = fminf(v, __shfl_down_sync(0xffffffffu, v, o));
    return v;
}
__device__ __forceinline__ float wmax(float v) {
#pragma unroll
    for (int o = 16; o > 0; o >>= 1) v = fmaxf(v, __shfl_down_sync(0xffffffffu, v, o));
    return v;
}

// Block-wide sum. Each call uses its own shared buffer (no reuse hazards).
__device__ __forceinline__ float bsum(float v, float* buf) {
    int lane = threadIdx.x & 31, w = threadIdx.x >> 5;
    v = wsum(v);
    if (lane == 0) buf[w] = v;
    __syncthreads();
    if (threadIdx.x < 32) {
        float x = (lane < NWARP) ? buf[lane] : 0.f;
        x = wsum(x);
        if (lane == 0) buf[0] = x;
    }
    __syncthreads();
    return buf[0];
}

__device__ __forceinline__ float bmin(float v, float* buf) {
    int lane = threadIdx.x & 31, w = threadIdx.x >> 5;
    v = wmin(v);
    if (lane == 0) buf[w] = v;
    __syncthreads();
    if (threadIdx.x < 32) {
        float x = (lane < NWARP) ? buf[lane] : 3.0e38f;
        x = wmin(x);
        if (lane == 0) buf[0] = x;
    }
    __syncthreads();
    return buf[0];
}

__device__ __forceinline__ float bmax(float v, float* buf) {
    int lane = threadIdx.x & 31, w = threadIdx.x >> 5;
    v = wmax(v);
    if (lane == 0) buf[w] = v;
    __syncthreads();
    if (threadIdx.x < 32) {
        float x = (lane < NWARP) ? buf[lane] : -3.0e38f;
        x = wmax(x);
        if (lane == 0) buf[0] = x;
    }
    __syncthreads();
    return buf[0];
}

// Block-wide "value at argmax(|value|)" reduction.
__device__ __forceinline__ float babsmax(float av, float vv, float* bufa, float* bufv) {
    int lane = threadIdx.x & 31, w = threadIdx.x >> 5;
#pragma unroll
    for (int o = 16; o > 0; o >>= 1) {
        float oa = __shfl_down_sync(0xffffffffu, av, o);
        float ov = __shfl_down_sync(0xffffffffu, vv, o);
        if (oa > av) { av = oa; vv = ov; }
    }
    if (lane == 0) { bufa[w] = av; bufv[w] = vv; }
    __syncthreads();
    if (threadIdx.x < 32) {
        float xa = (lane < NWARP) ? bufa[lane] : -1.f;
        float xv = (lane < NWARP) ? bufv[lane] : 0.f;
#pragma unroll
        for (int o = 16; o > 0; o >>= 1) {
            float oa = __shfl_down_sync(0xffffffffu, xa, o);
            float ov = __shfl_down_sync(0xffffffffu, xv, o);
            if (oa > xa) { xa = oa; xv = ov; }
        }
        if (lane == 0) bufv[0] = xv;
    }
    __syncthreads();
    return bufv[0];
}

__global__ void __launch_bounds__(BLOCK, 1)
spectral_rank2_kernel(const float* __restrict__ in, float* __restrict__ out) {
    __shared__ float bSc[NWARP], bSs[NWARP], bA[NWARP], bB[NWARP], bC[NWARP];
    __shared__ float bMn[NWARP], bMx[NWARP], bS2[NWARP], bAA[NWARP], bAV[NWARP];
    __shared__ float coef[2];

    const int t = threadIdx.x;

    // Phase 1: sigmoid -> (max_conf, v) -> row-normalized unit vector (c, s).
    float cc[K], ssv[K];
    float pc = 0.f, ps = 0.f;
#pragma unroll
    for (int k = 0; k < K; k++) {
        float x = in[t + k * BLOCK];                // coalesced
        float p = 1.f / (1.f + expf(-x));           // sigmoid
        float mc = fmaxf(p, 1.f - p);
        float vv = (1.f - mc) / (mc + 1e-10f);
        float nr = fmaxf(sqrtf(mc * mc + vv * vv), 1e-12f);
        float c = mc / nr, s = vv / nr;
        cc[k] = c; ssv[k] = s;
        pc += c; ps += s;
    }
    float Sc = bsum(pc, bSc);
    float Ss = bsum(ps, bSs);

    // Phase 2: degree, dis, u = dis*c, v = dis*s; Gram partials.
    float pa = 0.f, pb = 0.f, pcc = 0.f;
#pragma unroll
    for (int k = 0; k < K; k++) {
        float c = cc[k], s = ssv[k];
        float d = c * Sc + s * Ss;                  // row sum of A (includes self)
        float dis = 1.f / (sqrtf(d) + 1e-10f);
        float u = dis * c, v = dis * s;
        cc[k] = u; ssv[k] = v;                      // overwrite with (u, v)
        pa += u * u; pb += u * v; pcc += v * v;
    }
    float Ag = bsum(pa, bA);
    float Bg = bsum(pb, bB);
    float Cg = bsum(pcc, bC);

    // Phase 3: 2x2 eigensolve for the SECOND-largest eigenvalue of
    // G = [[a,b],[b,c]]; Fiedler vector = alpha*u + beta*v.
    if (t == 0) {
        double a = (double)Ag, b = (double)Bg, c = (double)Cg;
        double half = 0.5 * (a + c), diff = 0.5 * (a - c);
        double r = sqrt(diff * diff + b * b);
        double lam2 = half - r;
        double e1x = b,        e1y = lam2 - a;
        double e2x = lam2 - c, e2y = b;
        double n1 = e1x * e1x + e1y * e1y;
        double n2 = e2x * e2x + e2y * e2y;
        if (n1 >= n2) { coef[0] = (float)e1x; coef[1] = (float)e1y; }
        else          { coef[0] = (float)e2x; coef[1] = (float)e2y; }
    }
    __syncthreads();
    float al = coef[0], be = coef[1];

    // Phase 4: Fiedler values + reductions (min, max, sum of squares, sign pivot).
    float F[K];
    float pmn = 3.0e38f, pmx = -3.0e38f, ps2 = 0.f, paa = -1.f, pav = 0.f;
#pragma unroll
    for (int k = 0; k < K; k++) {
        float f = al * cc[k] + be * ssv[k];
        F[k] = f;
        pmn = fminf(pmn, f);
        pmx = fmaxf(pmx, f);
        ps2 += f * f;
        float af = fabsf(f);
        if (af > paa) { paa = af; pav = f; }
    }
    float Fmn = bmin(pmn, bMn);
    float Fmx = bmax(pmx, bMx);
    float S2  = bsum(ps2, bS2);
    float pivot = babsmax(paa, pav, bAA, bAV);

    // Phase 5: sign fix (eigh unit-norm first), then min-max normalize.
    float sgn  = (pivot >= 0.f) ? 1.f : -1.f;
    float invn = 1.f / sqrtf(S2);                   // matches eigh's unit-norm vector
    float gmn = (sgn > 0.f) ? Fmn * invn : -Fmx * invn;
    float gmx = (sgn > 0.f) ? Fmx * invn : -Fmn * invn;
    float scale = 1.f / (gmx - gmn + 1e-10f);
#pragma unroll
    for (int k = 0; k < K; k++) {
        float g = sgn * F[k] * invn;
        out[t + k * BLOCK] = (g - gmn) * scale;
    }
}

extern "C" void kernel_launch(void* const* d_in, const int* in_sizes, int n_in,
                              void* d_out, int out_size) {
    (void)in_sizes; (void)n_in; (void)out_size;
    const float* in = (const float*)d_in[0];
    float* out = (float*)d_out;
    spectral_rank2_kernel<<<1, BLOCK>>>(in, out);
}

// round 3
// speedup vs baseline: 2.1481x; 2.1481x over previous
#include <cuda_runtime.h>
#include <math.h>

#define BLOCK 1024
#define NWARP 32

__device__ __forceinline__ float wredsum(float x) {
#pragma unroll
    for (int o = 16; o > 0; o >>= 1) x += __shfl_down_sync(0xffffffffu, x, o);
    return x;
}
__device__ __forceinline__ float wredmax(float x) {
#pragma unroll
    for (int o = 16; o > 0; o >>= 1) x = fmaxf(x, __shfl_down_sync(0xffffffffu, x, o));
    return x;
}

__global__ void __launch_bounds__(BLOCK, 1)
spectral_rank2_kernel(const float4* __restrict__ in4, float4* __restrict__ out4) {
    __shared__ float sb[3][NWARP];
    __shared__ float r1[2], r2[3], r3[2];
    const int t = threadIdx.x;
    const int lane = t & 31, w = t >> 5;

    // ---- Phase 1: load + feature transform.
    // mc = sigmoid(|x|) = 1/(1+e), v = (1-mc)/(mc+1e-10) ~= e, e = exp(-|x|).
    // Row-normalized feature direction (mc, e) ~ (1, q)/sqrt(1+q^2), q = e(1+e).
    float4 x4 = in4[t];
    float xs[4] = {x4.x, x4.y, x4.z, x4.w};
    float c[4], s[4];
    float pc = 0.f, ps = 0.f;
#pragma unroll
    for (int k = 0; k < 4; k++) {
        float e = __expf(-fabsf(xs[k]));
        float q = fmaf(e, e, e);                 // e + e^2
        float cw = rsqrtf(fmaf(q, q, 1.f));      // c = 1/sqrt(1+q^2)
        float sw = q * cw;                       // s = q/sqrt(1+q^2)
        c[k] = cw; s[k] = sw;
        pc += cw; ps += sw;
    }
    // ---- R1: block sums Sc, Ss (one barrier pair, 2 values).
    {
        float a = wredsum(pc), b = wredsum(ps);
        if (lane == 0) { sb[0][w] = a; sb[1][w] = b; }
        __syncthreads();
        if (w == 0) {
            float a2 = wredsum(sb[0][lane]);
            float b2 = wredsum(sb[1][lane]);
            if (lane == 0) { r1[0] = a2; r1[1] = b2; }
        }
        __syncthreads();
    }
    const float Sc = r1[0], Ss = r1[1];

    // ---- Phase 2: degree -> dis -> (u,v); Gram partials of rank-2 subspace.
    float U[4], V[4];
    float pa = 0.f, pb = 0.f, pg = 0.f;
#pragma unroll
    for (int k = 0; k < 4; k++) {
        float d   = fmaf(c[k], Sc, s[k] * Ss);   // row sum of A
        float dis = rsqrtf(d);                   // 1/(sqrt(d)+1e-10), eps negligible
        float u = c[k] * dis, v = s[k] * dis;
        U[k] = u; V[k] = v;
        pa = fmaf(u, u, pa);
        pb = fmaf(u, v, pb);
        pg = fmaf(v, v, pg);
    }
    // ---- R2: Gram sums (a, b, g).
    {
        float a = wredsum(pa), b = wredsum(pb), g = wredsum(pg);
        if (lane == 0) { sb[0][w] = a; sb[1][w] = b; sb[2][w] = g; }
        __syncthreads();
        if (w == 0) {
            float a2 = wredsum(sb[0][lane]);
            float b2 = wredsum(sb[1][lane]);
            float g2 = wredsum(sb[2][lane]);
            if (lane == 0) { r2[0] = a2; r2[1] = b2; r2[2] = g2; }
        }
        __syncthreads();
    }
    const float A = r2[0], B = r2[1], C = r2[2];

    // ---- Phase 3: 2x2 eigensolve (second eigenvalue lam2 = (A+C)/2 - r) done
    // redundantly on every thread; numerically stable eigenvector branch.
    // Sign of the eigenvector is irrelevant (re-fixed below).
    float diff = 0.5f * (A - C);
    float rr = sqrtf(fmaf(diff, diff, B * B));
    float al, be;
    if (diff >= 0.f) { al = B;         be = -(diff + rr); }   // from row 1
    else             { al = rr - diff; be = -B;            }  // from row 2

    // ---- Phase 4: Fiedler values F = al*u + be*v; min/max via dual max.
    float F[4];
    float pmx = -3.0e38f, pnn = -3.0e38f;
#pragma unroll
    for (int k = 0; k < 4; k++) {
        float f = fmaf(al, U[k], be * V[k]);
        F[k] = f;
        pmx = fmaxf(pmx, f);
        pnn = fmaxf(pnn, -f);
    }
    // ---- R3: block max(f), max(-f).
    {
        float a = wredmax(pmx), b = wredmax(pnn);
        if (lane == 0) { sb[0][w] = a; sb[1][w] = b; }
        __syncthreads();
        if (w == 0) {
            float a2 = wredmax(sb[0][lane]);
            float b2 = wredmax(sb[1][lane]);
            if (lane == 0) { r3[0] = a2; r3[1] = b2; }
        }
        __syncthreads();
    }
    const float Fmx = r3[0], Fmn = -r3[1];

    // ---- Phase 5: sign fix at argmax|F| (it is the min or the max), min-max norm.
    float pivot = (fabsf(Fmx) >= fabsf(Fmn)) ? Fmx : Fmn;
    float sgn = (pivot >= 0.f) ? 1.f : -1.f;
    float mn = (sgn > 0.f) ? Fmn : -Fmx;
    float mx = (sgn > 0.f) ? Fmx : -Fmn;
    float scale = __fdividef(1.f, mx - mn + 1e-10f);

    float4 o;
    o.x = (sgn * F[0] - mn) * scale;
    o.y = (sgn * F[1] - mn) * scale;
    o.z = (sgn * F[2] - mn) * scale;
    o.w = (sgn * F[3] - mn) * scale;
    out4[t] = o;
}

extern "C" void kernel_launch(void* const* d_in, const int* in_sizes, int n_in,
                              void* d_out, int out_size) {
    (void)in_sizes; (void)n_in; (void)out_size;
    const float4* in = (const float4*)d_in[0];
    float4* out = (float4*)d_out;
    spectral_rank2_kernel<<<1, BLOCK>>>(in, out);
}